// round 8
// baseline (speedup 1.0000x reference)
#include <cuda_runtime.h>
#include <math.h>

#define CCH 256
#define BAT 16
#define HDIM 16
#define SPATIAL 16384            // 128*128
#define BC (BAT*CCH)             // 4096 planes
#define CHUNK_B 4                // batches per chunk (64 MiB < 126 MB L2)
#define NCHUNK (BAT/CHUNK_B)     // 4
#define CHUNK_PLANES (CHUNK_B*CCH)  // 1024

// Scratch (device globals — no allocations allowed)
__device__ float g_mean[BC];
__device__ float g_std[BC];
__device__ float g_mask[BC];
__device__ unsigned int g_done[BAT];   // monotonic last-block counters

__device__ __forceinline__ float warp_sum(float v) {
#pragma unroll
    for (int o = 16; o > 0; o >>= 1) v += __shfl_xor_sync(0xffffffffu, v, o);
    return v;
}

__device__ __forceinline__ float dot4(float4 a, float4 b, float acc) {
    acc = fmaf(a.x, b.x, acc);
    acc = fmaf(a.y, b.y, acc);
    acc = fmaf(a.z, b.z, acc);
    return fmaf(a.w, b.w, acc);
}

// ---------------------------------------------------------------------------
// MLP chain for one batch element, executed by one 256-thread block.
// ---------------------------------------------------------------------------
__device__ void mlp_block(
    int b, int tid,
    const float* __restrict__ sw1, const float* __restrict__ sb1,
    const float* __restrict__ sw2, const float* __restrict__ sb2,
    const float* __restrict__ mw1, const float* __restrict__ mb1,
    const float* __restrict__ mw2, const float* __restrict__ mb2,
    const float* __restrict__ bw,  const float* __restrict__ bb,
    const float* __restrict__ fw1, const float* __restrict__ fb1,
    const float* __restrict__ fw2, const float* __restrict__ fb2)
{
    const int w = tid >> 5, l = tid & 31;

    __shared__ float sdesc[2 * CCH];   // [std(256) | mean(256)]
    __shared__ float h[2 * HDIM];
    __shared__ float fused[2 * CCH];
    __shared__ float bott[CCH];
    __shared__ float fh[HDIM];

    sdesc[tid]       = g_std[b * CCH + tid];
    sdesc[CCH + tid] = g_mean[b * CCH + tid];
    __syncthreads();

    const float4* sdesc4 = (const float4*)sdesc;

    // SE hidden layers: 32 outputs (16 std + 16 mean).
#pragma unroll
    for (int j = 0; j < 4; j++) {
        const int o  = w * 4 + j;
        const int hh = o & (HDIM - 1);
        const float4* w1 = (const float4*)(((o < HDIM) ? sw1 : mw1) + hh * CCH);
        const float4* d  = (o < HDIM) ? sdesc4 : (sdesc4 + CCH / 4);
        float acc = 0.f;
#pragma unroll
        for (int k = 0; k < 2; k++)
            acc = dot4(w1[k * 32 + l], d[k * 32 + l], acc);
        acc = warp_sum(acc);
        if (l == 0) {
            const float bias = (o < HDIM) ? sb1[hh] : mb1[hh];
            h[o] = fmaxf(acc + bias, 0.f);
        }
    }
    __syncthreads();

    // SE output layers -> fused [512].
    {
        float a1 = sb2[tid], a2 = mb2[tid];
        const float4* s2 = (const float4*)(sw2 + tid * HDIM);
        const float4* m2 = (const float4*)(mw2 + tid * HDIM);
        const float4* h4a = (const float4*)h;
        const float4* h4b = (const float4*)(h + HDIM);
#pragma unroll
        for (int q = 0; q < 4; q++) {
            a1 = dot4(s2[q], h4a[q], a1);
            a2 = dot4(m2[q], h4b[q], a2);
        }
        fused[tid]       = a1;
        fused[CCH + tid] = a2;
    }
    __syncthreads();

    // Bottleneck 512 -> 256 + relu.
    const float4* fused4 = (const float4*)fused;
    for (int r = 0; r < 32; r += 2) {
        const int c0 = w + r * 8;
        const int c1 = w + (r + 1) * 8;
        const float4* b0 = (const float4*)(bw + c0 * (2 * CCH));
        const float4* b1 = (const float4*)(bw + c1 * (2 * CCH));
        float a0 = 0.f, a1 = 0.f;
#pragma unroll
        for (int k = 0; k < 4; k++) {
            const float4 f = fused4[k * 32 + l];
            a0 = dot4(b0[k * 32 + l], f, a0);
            a1 = dot4(b1[k * 32 + l], f, a1);
        }
        a0 = warp_sum(a0);
        a1 = warp_sum(a1);
        if (l == 0) {
            bott[c0] = fmaxf(a0 + bb[c0], 0.f);
            bott[c1] = fmaxf(a1 + bb[c1], 0.f);
        }
    }
    __syncthreads();

    // Final SE hidden: 16 outputs.
    const float4* bott4 = (const float4*)bott;
#pragma unroll
    for (int j = 0; j < 2; j++) {
        const int o = w * 2 + j;
        const float4* w1 = (const float4*)(fw1 + o * CCH);
        float acc = 0.f;
#pragma unroll
        for (int k = 0; k < 2; k++)
            acc = dot4(w1[k * 32 + l], bott4[k * 32 + l], acc);
        acc = warp_sum(acc);
        if (l == 0) fh[o] = fmaxf(acc + fb1[o], 0.f);
    }
    __syncthreads();

    // Final SE output + sigmoid -> mask.
    {
        float acc = fb2[tid];
        const float4* f2  = (const float4*)(fw2 + tid * HDIM);
        const float4* fh4 = (const float4*)fh;
#pragma unroll
        for (int q = 0; q < 4; q++) acc = dot4(f2[q], fh4[q], acc);
        g_mask[b * CCH + tid] = 1.f / (1.f + expf(-acc));
    }
}

// ---------------------------------------------------------------------------
// Stats for one chunk of 4 batches (1024 planes, one block per plane).
// PLAIN cached loads: deliberately seed L2 with the 64 MiB chunk for the
// apply pass. Last block per batch (monotonic counter) runs the MLP.
// ---------------------------------------------------------------------------
__global__ void __launch_bounds__(256) stats_mlp_kernel(
    const float* __restrict__ x, int chunk,
    const float* __restrict__ sw1, const float* __restrict__ sb1,
    const float* __restrict__ sw2, const float* __restrict__ sb2,
    const float* __restrict__ mw1, const float* __restrict__ mb1,
    const float* __restrict__ mw2, const float* __restrict__ mb2,
    const float* __restrict__ bw,  const float* __restrict__ bb,
    const float* __restrict__ fw1, const float* __restrict__ fb1,
    const float* __restrict__ fw2, const float* __restrict__ fb2)
{
    const int tid = threadIdx.x;
    const int bc  = chunk * CHUNK_PLANES + blockIdx.x;
    const int b   = bc >> 8;               // batch index
    const float4* __restrict__ xp = (const float4*)(x + (size_t)bc * SPATIAL);

    float s = 0.f, s2 = 0.f;
#pragma unroll
    for (int i = 0; i < SPATIAL / 4 / 256; i++) {
        float4 v = xp[i * 256 + tid];      // cached: seed L2 for apply pass
        s  += (v.x + v.y) + (v.z + v.w);
        s2 += (v.x * v.x + v.y * v.y) + (v.z * v.z + v.w * v.w);
    }
    s  = warp_sum(s);
    s2 = warp_sum(s2);
    __shared__ float ws[8], ws2[8];
    const int w = tid >> 5, l = tid & 31;
    if (l == 0) { ws[w] = s; ws2[w] = s2; }
    __syncthreads();

    __shared__ bool is_last;
    if (tid == 0) {
        float ts = 0.f, ts2 = 0.f;
#pragma unroll
        for (int i = 0; i < 8; i++) { ts += ws[i]; ts2 += ws2[i]; }
        const float inv = 1.f / (float)SPATIAL;
        float mean = ts * inv;
        float var  = ts2 * inv - mean * mean;
        g_mean[bc] = mean;
        g_std[bc]  = sqrtf(fmaxf(var, 0.f));
        __threadfence();                    // publish stats before counting in
        unsigned int cnt = atomicAdd(&g_done[b], 1u) + 1u;
        is_last = ((cnt & 255u) == 0u);     // monotonic: replay-safe
        if (is_last) __threadfence();       // acquire others' stats writes
    }
    __syncthreads();

    if (is_last) {
        mlp_block(b, tid, sw1, sb1, sw2, sb2, mw1, mb1, mw2, mb2,
                  bw, bb, fw1, fb1, fw2, fb2);
    }
}

// ---------------------------------------------------------------------------
// Apply for one chunk: out = x * mask.
//   reads:  __ldcs — hit the L2 copy seeded by stats, evict-first (dead data)
//   writes: __stwt — WRITE-THROUGH. out is never re-read; keeping it out of
//           L2 as dirty lines prevents the next stats chunk's reads from
//           stalling behind write-back drain (the R6 failure mode).
// Each block: half a plane (2048 consecutive float4s), one mask scalar.
// ---------------------------------------------------------------------------
__global__ void __launch_bounds__(256) apply_kernel(const float* __restrict__ x,
                                                    float* __restrict__ out,
                                                    int chunk) {
    const int plane = chunk * CHUNK_PLANES + (blockIdx.x >> 1);
    const int half  = blockIdx.x & 1;
    const size_t base = (size_t)plane * (SPATIAL / 4) + half * 2048 + threadIdx.x;
    const float m = g_mask[plane];
    const float4* __restrict__ xp = (const float4*)x + base;
    float4* __restrict__ op = (float4*)out + base;

    float4 v[8];
#pragma unroll
    for (int i = 0; i < 8; i++) v[i] = __ldcs(&xp[i * 256]);
#pragma unroll
    for (int i = 0; i < 8; i++) {
        float4 t = v[i];
        t.x *= m; t.y *= m; t.z *= m; t.w *= m;
        __stwt(&op[i * 256], t);
    }
}

extern "C" void kernel_launch(void* const* d_in, const int* in_sizes, int n_in,
                              void* d_out, int out_size) {
    const float* x   = (const float*)d_in[0];
    const float* sw1 = (const float*)d_in[1];
    const float* sb1 = (const float*)d_in[2];
    const float* sw2 = (const float*)d_in[3];
    const float* sb2 = (const float*)d_in[4];
    const float* mw1 = (const float*)d_in[5];
    const float* mb1 = (const float*)d_in[6];
    const float* mw2 = (const float*)d_in[7];
    const float* mb2 = (const float*)d_in[8];
    const float* bw  = (const float*)d_in[9];
    const float* bb  = (const float*)d_in[10];
    const float* fw1 = (const float*)d_in[11];
    const float* fb1 = (const float*)d_in[12];
    const float* fw2 = (const float*)d_in[13];
    const float* fb2 = (const float*)d_in[14];
    float* out = (float*)d_out;

    for (int c = 0; c < NCHUNK; c++) {
        stats_mlp_kernel<<<CHUNK_PLANES, 256>>>(x, c,
            sw1, sb1, sw2, sb2, mw1, mb1, mw2, mb2,
            bw, bb, fw1, fb1, fw2, fb2);
        apply_kernel<<<CHUNK_PLANES * 2, 256>>>(x, out, c);
    }
}

// round 9
// speedup vs baseline: 1.5747x; 1.5747x over previous
#include <cuda_runtime.h>
#include <math.h>

#define CCH 256
#define BAT 16
#define HDIM 16
#define SPATIAL 16384      // 128*128
#define BC (BAT*CCH)       // 4096 planes

// Scratch (device globals — no allocations allowed)
__device__ float g_mean[BC];
__device__ float g_std[BC];
__device__ float g_mask[BC];
__device__ unsigned int g_done[BAT];   // monotonic last-block counters

__device__ __forceinline__ float warp_sum(float v) {
#pragma unroll
    for (int o = 16; o > 0; o >>= 1) v += __shfl_xor_sync(0xffffffffu, v, o);
    return v;
}

__device__ __forceinline__ float dot4(float4 a, float4 b, float acc) {
    acc = fmaf(a.x, b.x, acc);
    acc = fmaf(a.y, b.y, acc);
    acc = fmaf(a.z, b.z, acc);
    return fmaf(a.w, b.w, acc);
}

// ---------------------------------------------------------------------------
// MLP chain for one batch element, executed by one 256-thread block.
// Warp-cooperative coalesced matvecs, float4 loads.
// ---------------------------------------------------------------------------
__device__ void mlp_block(
    int b, int tid,
    const float* __restrict__ sw1, const float* __restrict__ sb1,
    const float* __restrict__ sw2, const float* __restrict__ sb2,
    const float* __restrict__ mw1, const float* __restrict__ mb1,
    const float* __restrict__ mw2, const float* __restrict__ mb2,
    const float* __restrict__ bw,  const float* __restrict__ bb,
    const float* __restrict__ fw1, const float* __restrict__ fb1,
    const float* __restrict__ fw2, const float* __restrict__ fb2)
{
    const int w = tid >> 5, l = tid & 31;

    __shared__ float sdesc[2 * CCH];   // [std(256) | mean(256)]
    __shared__ float h[2 * HDIM];
    __shared__ float fused[2 * CCH];
    __shared__ float bott[CCH];
    __shared__ float fh[HDIM];

    sdesc[tid]       = g_std[b * CCH + tid];
    sdesc[CCH + tid] = g_mean[b * CCH + tid];
    __syncthreads();

    const float4* sdesc4 = (const float4*)sdesc;

    // SE hidden layers: 32 outputs (16 std + 16 mean).
#pragma unroll
    for (int j = 0; j < 4; j++) {
        const int o  = w * 4 + j;
        const int hh = o & (HDIM - 1);
        const float4* w1 = (const float4*)(((o < HDIM) ? sw1 : mw1) + hh * CCH);
        const float4* d  = (o < HDIM) ? sdesc4 : (sdesc4 + CCH / 4);
        float acc = 0.f;
#pragma unroll
        for (int k = 0; k < 2; k++)
            acc = dot4(w1[k * 32 + l], d[k * 32 + l], acc);
        acc = warp_sum(acc);
        if (l == 0) {
            const float bias = (o < HDIM) ? sb1[hh] : mb1[hh];
            h[o] = fmaxf(acc + bias, 0.f);
        }
    }
    __syncthreads();

    // SE output layers -> fused [512].
    {
        float a1 = sb2[tid], a2 = mb2[tid];
        const float4* s2 = (const float4*)(sw2 + tid * HDIM);
        const float4* m2 = (const float4*)(mw2 + tid * HDIM);
        const float4* h4a = (const float4*)h;
        const float4* h4b = (const float4*)(h + HDIM);
#pragma unroll
        for (int q = 0; q < 4; q++) {
            a1 = dot4(s2[q], h4a[q], a1);
            a2 = dot4(m2[q], h4b[q], a2);
        }
        fused[tid]       = a1;
        fused[CCH + tid] = a2;
    }
    __syncthreads();

    // Bottleneck 512 -> 256 + relu.
    const float4* fused4 = (const float4*)fused;
    for (int r = 0; r < 32; r += 2) {
        const int c0 = w + r * 8;
        const int c1 = w + (r + 1) * 8;
        const float4* b0 = (const float4*)(bw + c0 * (2 * CCH));
        const float4* b1 = (const float4*)(bw + c1 * (2 * CCH));
        float a0 = 0.f, a1 = 0.f;
#pragma unroll
        for (int k = 0; k < 4; k++) {
            const float4 f = fused4[k * 32 + l];
            a0 = dot4(b0[k * 32 + l], f, a0);
            a1 = dot4(b1[k * 32 + l], f, a1);
        }
        a0 = warp_sum(a0);
        a1 = warp_sum(a1);
        if (l == 0) {
            bott[c0] = fmaxf(a0 + bb[c0], 0.f);
            bott[c1] = fmaxf(a1 + bb[c1], 0.f);
        }
    }
    __syncthreads();

    // Final SE hidden: 16 outputs.
    const float4* bott4 = (const float4*)bott;
#pragma unroll
    for (int j = 0; j < 2; j++) {
        const int o = w * 2 + j;
        const float4* w1 = (const float4*)(fw1 + o * CCH);
        float acc = 0.f;
#pragma unroll
        for (int k = 0; k < 2; k++)
            acc = dot4(w1[k * 32 + l], bott4[k * 32 + l], acc);
        acc = warp_sum(acc);
        if (l == 0) fh[o] = fmaxf(acc + fb1[o], 0.f);
    }
    __syncthreads();

    // Final SE output + sigmoid -> mask.
    {
        float acc = fb2[tid];
        const float4* f2  = (const float4*)(fw2 + tid * HDIM);
        const float4* fh4 = (const float4*)fh;
#pragma unroll
        for (int q = 0; q < 4; q++) acc = dot4(f2[q], fh4[q], acc);
        g_mask[b * CCH + tid] = 1.f / (1.f + expf(-acc));
    }
}

// ---------------------------------------------------------------------------
// Stats over ALL 4096 planes (one block per plane; proven 80% DRAM shape).
// PLAIN cached loads seed L2 with the tail of x for the reverse-order apply.
// Last block per batch (monotonic counter; replay-safe) runs that batch's MLP.
// ---------------------------------------------------------------------------
__global__ void __launch_bounds__(256) stats_mlp_kernel(
    const float* __restrict__ x,
    const float* __restrict__ sw1, const float* __restrict__ sb1,
    const float* __restrict__ sw2, const float* __restrict__ sb2,
    const float* __restrict__ mw1, const float* __restrict__ mb1,
    const float* __restrict__ mw2, const float* __restrict__ mb2,
    const float* __restrict__ bw,  const float* __restrict__ bb,
    const float* __restrict__ fw1, const float* __restrict__ fb1,
    const float* __restrict__ fw2, const float* __restrict__ fb2)
{
    const int tid = threadIdx.x;
    const int bc  = blockIdx.x;
    const int b   = bc >> 8;               // batch index
    const float4* __restrict__ xp = (const float4*)(x + (size_t)bc * SPATIAL);

    float s = 0.f, s2 = 0.f;
#pragma unroll
    for (int i = 0; i < SPATIAL / 4 / 256; i++) {
        float4 v = xp[i * 256 + tid];      // cached: seed L2 for apply pass
        s  += (v.x + v.y) + (v.z + v.w);
        s2 += (v.x * v.x + v.y * v.y) + (v.z * v.z + v.w * v.w);
    }
    s  = warp_sum(s);
    s2 = warp_sum(s2);
    __shared__ float ws[8], ws2[8];
    const int w = tid >> 5, l = tid & 31;
    if (l == 0) { ws[w] = s; ws2[w] = s2; }
    __syncthreads();

    __shared__ bool is_last;
    if (tid == 0) {
        float ts = 0.f, ts2 = 0.f;
#pragma unroll
        for (int i = 0; i < 8; i++) { ts += ws[i]; ts2 += ws2[i]; }
        const float inv = 1.f / (float)SPATIAL;
        float mean = ts * inv;
        float var  = ts2 * inv - mean * mean;
        g_mean[bc] = mean;
        g_std[bc]  = sqrtf(fmaxf(var, 0.f));
        __threadfence();                    // publish stats before counting in
        unsigned int cnt = atomicAdd(&g_done[b], 1u) + 1u;
        is_last = ((cnt & 255u) == 0u);     // monotonic: replay-safe
        if (is_last) __threadfence();       // acquire others' stats writes
    }
    __syncthreads();

    if (is_last) {
        mlp_block(b, tid, sw1, sb1, sw2, sb2, mw1, mb1, mw2, mb2,
                  bw, bb, fw1, fb1, fw2, fb2);
    }
}

// ---------------------------------------------------------------------------
// Apply: out = x * mask[b,c], planes processed in DESCENDING order so the
// first reads hit the x tail that stats just left in L2 (~126 MB ≈ half of x).
//   reads:  __ldcs  (single-use: evict-first after hit)
//   writes: __stwt  (never re-read: keep out of L2 entirely)
// Each block: half a plane (2048 consecutive float4s), one mask scalar.
// ---------------------------------------------------------------------------
__global__ void __launch_bounds__(256) apply_kernel(const float* __restrict__ x,
                                                    float* __restrict__ out) {
    const int plane = BC - 1 - (blockIdx.x >> 1);      // reverse plane order
    const int half  = blockIdx.x & 1;
    const size_t base = (size_t)plane * (SPATIAL / 4) + half * 2048 + threadIdx.x;
    const float m = g_mask[plane];
    const float4* __restrict__ xp = (const float4*)x + base;
    float4* __restrict__ op = (float4*)out + base;

    float4 v[8];
#pragma unroll
    for (int i = 0; i < 8; i++) v[i] = __ldcs(&xp[i * 256]);
#pragma unroll
    for (int i = 0; i < 8; i++) {
        float4 t = v[i];
        t.x *= m; t.y *= m; t.z *= m; t.w *= m;
        __stwt(&op[i * 256], t);
    }
}

extern "C" void kernel_launch(void* const* d_in, const int* in_sizes, int n_in,
                              void* d_out, int out_size) {
    const float* x   = (const float*)d_in[0];
    const float* sw1 = (const float*)d_in[1];
    const float* sb1 = (const float*)d_in[2];
    const float* sw2 = (const float*)d_in[3];
    const float* sb2 = (const float*)d_in[4];
    const float* mw1 = (const float*)d_in[5];
    const float* mb1 = (const float*)d_in[6];
    const float* mw2 = (const float*)d_in[7];
    const float* mb2 = (const float*)d_in[8];
    const float* bw  = (const float*)d_in[9];
    const float* bb  = (const float*)d_in[10];
    const float* fw1 = (const float*)d_in[11];
    const float* fb1 = (const float*)d_in[12];
    const float* fw2 = (const float*)d_in[13];
    const float* fb2 = (const float*)d_in[14];
    float* out = (float*)d_out;

    stats_mlp_kernel<<<BC, 256>>>(x,
        sw1, sb1, sw2, sb2, mw1, mb1, mw2, mb2,
        bw, bb, fw1, fb1, fw2, fb2);
    apply_kernel<<<BC * 2, 256>>>(x, out);
}